// round 10
// baseline (speedup 1.0000x reference)
#include <cuda_runtime.h>
#include <math.h>

#define THREADS 256
#define MAXN 4096
#define NB0 2048        // level-0 bins (top 11 bits of key)
#define SH0 21          // 32 - 11
#define MARGIN 64       // sample-rank margin (~5 sigma)
#define WCAP 64         // max bracket width in bins

// Order-preserving float->uint key: monotonic increasing with float value.
__device__ __forceinline__ unsigned f2key(float v) {
    unsigned u = __float_as_uint(v);
    return u ^ (unsigned)(((int)u >> 31) | 0x80000000u);
}
__device__ __forceinline__ float key2f(unsigned key) {
    unsigned u = (key & 0x80000000u) ? (key ^ 0x80000000u) : ~key;
    return __uint_as_float(u);
}

// Warp-collective over NB0=2048 bins: find bins containing count-ranks r1<=r2.
// DESC: ranks counted from top bin downward. Lane owns bins [64L, 64L+64).
template<bool DESC>
__device__ __forceinline__ void resolve_bins2(const unsigned* __restrict__ hist,
                                              int r1, int r2, int lane,
                                              unsigned &b1, unsigned &b2)
{
    const uint4* h4 = (const uint4*)hist;
    unsigned s = 0;
    #pragma unroll
    for (int j = 0; j < 16; j++) {
        uint4 c = h4[lane * 16 + j];
        s += c.x + c.y + c.z + c.w;
    }
    unsigned p = s;
    if (DESC) {
        #pragma unroll
        for (int o = 1; o < 32; o <<= 1) {
            unsigned t = __shfl_down_sync(0xFFFFFFFFu, p, o);
            if (lane + o < 32) p += t;
        }
    } else {
        #pragma unroll
        for (int o = 1; o < 32; o <<= 1) {
            unsigned t = __shfl_up_sync(0xFFFFFFFFu, p, o);
            if (lane >= o) p += t;
        }
    }
    unsigned excl = p - s;
    #pragma unroll
    for (int q = 0; q < 2; q++) {
        int r = q ? r2 : r1;
        bool cross = ((int)excl < r) && ((int)p >= r);
        unsigned m = __ballot_sync(0xFFFFFFFFu, cross);
        int src = __ffs(m) - 1;
        unsigned bsel = 0;
        if (cross) {
            unsigned cum = excl;
            if (DESC) {
                for (int b = lane * 64 + 63; b >= lane * 64; --b) {
                    cum += hist[b];
                    if ((int)cum >= r) { bsel = (unsigned)b; break; }
                }
            } else {
                for (int b = lane * 64; b < lane * 64 + 64; ++b) {
                    cum += hist[b];
                    if ((int)cum >= r) { bsel = (unsigned)b; break; }
                }
            }
        }
        unsigned bb = __shfl_sync(0xFFFFFFFFu, bsel, src);
        if (q) b2 = bb; else b1 = bb;
    }
}

// Warp-collective small resolve (NB in {32,256}): bin containing krem-th element.
template<int NB, bool DESC>
__device__ __forceinline__ void resolve_small(const unsigned* __restrict__ hist, int krem,
                                              int lane, unsigned &bin, int &krem_out)
{
    constexpr int BPL = NB / 32;
    unsigned s = 0;
    #pragma unroll
    for (int j = 0; j < BPL; j++) {
        int b = DESC ? (NB - 1 - (lane * BPL + j)) : (lane * BPL + j);
        s += hist[b];
    }
    unsigned p = s;
    #pragma unroll
    for (int o = 1; o < 32; o <<= 1) {
        unsigned t = __shfl_up_sync(0xFFFFFFFFu, p, o);
        if (lane >= o) p += t;
    }
    unsigned excl = p - s;
    bool cross = (excl < (unsigned)krem) && (p >= (unsigned)krem);
    unsigned m = __ballot_sync(0xFFFFFFFFu, cross);
    int src = __ffs(m) - 1;
    unsigned bsel = 0; int k2 = 0;
    if (cross) {
        unsigned cum = excl;
        #pragma unroll
        for (int j = 0; j < BPL; j++) {
            int b = DESC ? (NB - 1 - (lane * BPL + j)) : (lane * BPL + j);
            unsigned c = hist[b];
            if (cum + c >= (unsigned)krem) { bsel = (unsigned)b; k2 = krem - (int)cum; break; }
            cum += c;
        }
    }
    bin = __shfl_sync(0xFFFFFFFFu, bsel, src);
    krem_out = __shfl_sync(0xFFFFFFFFu, k2, src);
}

__global__ void __launch_bounds__(THREADS, 8)
wildcat_kernel(const float* __restrict__ x, float* __restrict__ out,
               int n, int kmax, int kmin, float alpha)
{
    // union: level-0 hist (2048 u32, first 8KB) / candidate values (4096 f, 16KB)
    __shared__ unsigned s_mem[MAXN];
    __shared__ unsigned s_subh[512];      // sublevel hists: [0:256)=H, [256:512)=L
    __shared__ unsigned s_bh[2 * WCAP];   // bracket hists: [0:64)=H, [64:128)=L
    __shared__ unsigned s_bLoH, s_bHiH, s_bLoL, s_bHiL;
    __shared__ int      s_cntH, s_cntL, s_cA, s_cB;
    __shared__ int      s_thH, s_thL, s_krH, s_krL, s_missH, s_missL;
    __shared__ int      s_redi[2][THREADS / 32];
    __shared__ float    s_redf[2][THREADS / 32];
    float* s_val = (float*)s_mem;

    const int tid  = threadIdx.x;
    const int lane = tid & 31;
    const int wid  = tid >> 5;
    const long long row = blockIdx.x;
    const float* __restrict__ xr = x + row * (long long)n;

    const int n4 = n >> 2;
    const float4* __restrict__ xr4 = (const float4*)xr;
    const int nv4 = (n4 / THREADS) * THREADS;
    const int ns = n >> 2;                // sample count (every 4th element)

    // ---- clear level-0 hist ----
    for (int b = tid; b < NB0; b += THREADS) s_mem[b] = 0;
    __syncthreads();

    // ===== pass 1: SAMPLED 11-bit histogram (1/4 of elements) ==================
    for (int s = tid; s < ns; s += THREADS)
        atomicAdd(&s_mem[f2key(xr[4 * s]) >> SH0], 1u);
    __syncthreads();

    // ---- bracket resolve from sample (two warps in parallel) ----
    if (wid == 0) {
        int ks = min(ns, max(1, (kmax + 2) >> 2));
        int r1 = max(1, ks - MARGIN), r2 = min(ns, ks + MARGIN);
        unsigned bHi, bLo;
        resolve_bins2<true>(s_mem, r1, r2, lane, bHi, bLo);
        if (lane == 0) { s_bHiH = bHi; s_bLoH = bLo; }
    } else if (wid == 1) {
        int ks = min(ns, max(1, (kmin + 2) >> 2));
        int r1 = max(1, ks - MARGIN), r2 = min(ns, ks + MARGIN);
        unsigned bLo, bHi;
        resolve_bins2<false>(s_mem, r1, r2, lane, bLo, bHi);
        if (lane == 0) { s_bLoL = bLo; s_bHiL = bHi; }
    }
    __syncthreads();

    bool haveBrackets =
        (s_bHiH - s_bLoH < WCAP) && (s_bHiL - s_bLoL < WCAP) && (s_bHiL < s_bLoH);

    float sumT, sumB;
    bool sameBin;

    while (true) {
        if (!haveBrackets) {
            // ---- exact fallback: full-element histogram ----
            __syncthreads();
            for (int b = tid; b < NB0; b += THREADS) s_mem[b] = 0;
            __syncthreads();
            for (int i = tid; i < nv4; i += THREADS) {
                float4 v = xr4[i];
                atomicAdd(&s_mem[f2key(v.x) >> SH0], 1u);
                atomicAdd(&s_mem[f2key(v.y) >> SH0], 1u);
                atomicAdd(&s_mem[f2key(v.z) >> SH0], 1u);
                atomicAdd(&s_mem[f2key(v.w) >> SH0], 1u);
            }
            for (int i = nv4 * 4 + tid; i < n; i += THREADS)
                atomicAdd(&s_mem[f2key(xr[i]) >> SH0], 1u);
            __syncthreads();
            if (wid == 0) {
                unsigned b1, b2;
                resolve_bins2<true>(s_mem, kmax, kmax, lane, b1, b2);
                if (lane == 0) { s_bLoH = b1; s_bHiH = b1; }
            } else if (wid == 1) {
                unsigned b1, b2;
                resolve_bins2<false>(s_mem, kmin, kmin, lane, b1, b2);
                if (lane == 0) { s_bLoL = b1; s_bHiL = b1; }
            }
            __syncthreads();
        }

        // ---- pass-2 state ----
        if (tid == 0) { s_cntH = 0; s_cntL = 0; s_cA = 0; s_cB = 0; }
        if (tid < 2 * WCAP) s_bh[tid] = 0;
        __syncthreads();

        const unsigned bLoH = s_bLoH, bHiH = s_bHiH, bLoL = s_bLoL, bHiL = s_bHiL;
        sameBin = (bLoH == bLoL) && (bHiH == bHiL);

        // ===== pass 2: full sweep — bulk sums + bracket compaction =============
        sumT = 0.0f; sumB = 0.0f;
        int cA = 0, cB = 0;
        for (int i = tid; i < nv4; i += THREADS) {
            float4 v = xr4[i];
            #pragma unroll
            for (int j = 0; j < 4; j++) {
                float f = (j == 0) ? v.x : (j == 1) ? v.y : (j == 2) ? v.z : v.w;
                unsigned bin = f2key(f) >> SH0;
                if (bin > bHiH) { sumT += f; cA++; }
                else if (bin >= bLoH) {
                    int p = atomicAdd(&s_cntH, 1);
                    s_val[p] = f;
                    atomicAdd(&s_bh[bin - bLoH], 1u);
                }
                if (bin < bLoL) { sumB += f; cB++; }
                else if (bin <= bHiL && !sameBin) {
                    int p = atomicAdd(&s_cntL, 1);
                    s_val[MAXN - 1 - p] = f;
                    atomicAdd(&s_bh[WCAP + bin - bLoL], 1u);
                }
            }
        }
        for (int i = nv4 * 4 + tid; i < n; i += THREADS) {
            float f = xr[i];
            unsigned bin = f2key(f) >> SH0;
            if (bin > bHiH) { sumT += f; cA++; }
            else if (bin >= bLoH) {
                int p = atomicAdd(&s_cntH, 1);
                s_val[p] = f;
                atomicAdd(&s_bh[bin - bLoH], 1u);
            }
            if (bin < bLoL) { sumB += f; cB++; }
            else if (bin <= bHiL && !sameBin) {
                int p = atomicAdd(&s_cntL, 1);
                s_val[MAXN - 1 - p] = f;
                atomicAdd(&s_bh[WCAP + bin - bLoL], 1u);
            }
        }
        // block-reduce exact above/below counts
        #pragma unroll
        for (int o = 16; o > 0; o >>= 1) {
            cA += __shfl_xor_sync(0xFFFFFFFFu, cA, o);
            cB += __shfl_xor_sync(0xFFFFFFFFu, cB, o);
        }
        if (lane == 0) { s_redi[0][wid] = cA; s_redi[1][wid] = cB; }
        __syncthreads();
        if (tid == 0) {
            int a = 0, b = 0;
            #pragma unroll
            for (int w = 0; w < THREADS / 32; ++w) { a += s_redi[0][w]; b += s_redi[1][w]; }
            s_cA = a; s_cB = b;
        }
        __syncthreads();

        // ---- exact theta-bin resolution inside brackets ----
        if (tid == 0) {
            int cAbove = s_cA, miss = 1;
            if (kmax > cAbove) {
                int cum = cAbove;
                for (int d = (int)bHiH; d >= (int)bLoH; --d) {
                    int c = (int)s_bh[d - (int)bLoH];
                    if (cum + c >= kmax) { s_thH = d; s_krH = kmax - cum; miss = 0; break; }
                    cum += c;
                }
            }
            s_missH = miss;
        }
        if (tid == 32) {
            int cBelow = s_cB, miss = 1;
            int base = sameBin ? 0 : WCAP;
            int lo = (int)(sameBin ? bLoH : bLoL);
            int hi = (int)(sameBin ? bHiH : bHiL);
            if (kmin > cBelow) {
                int cum = cBelow;
                for (int d = lo; d <= hi; ++d) {
                    int c = (int)s_bh[base + d - lo];
                    if (cum + c >= kmin) { s_thL = d; s_krL = kmin - cum; miss = 0; break; }
                    cum += c;
                }
            }
            s_missL = miss;
        }
        __syncthreads();
        bool ok = (s_missH == 0) && (s_missL == 0);
        if (ok) break;
        haveBrackets = false;      // exact rebuild (can only happen once)
        __syncthreads();
    }

    const int cntH = s_cntH;
    const int cntL = sameBin ? cntH : s_cntL;
    const unsigned thH = (unsigned)s_thH;   // 11-bit theta bins
    const unsigned thL = (unsigned)s_thL;

    // ===== sublevel 1: bits 20..13 (256 bins), filtered to theta bin ==========
    s_subh[tid] = 0;
    s_subh[tid + 256] = 0;
    __syncthreads();
    for (int t = tid; t < cntH; t += THREADS) {
        unsigned key = f2key(s_val[t]);
        if ((key >> SH0) == thH) atomicAdd(&s_subh[(key >> 13) & 0xFFu], 1u);
    }
    for (int t = tid; t < cntL; t += THREADS) {
        float f = sameBin ? s_val[t] : s_val[MAXN - 1 - t];
        unsigned key = f2key(f);
        if ((key >> SH0) == thL) atomicAdd(&s_subh[256 + ((key >> 13) & 0xFFu)], 1u);
    }
    __syncthreads();
    if (wid == 0) {
        unsigned b; int k2;
        resolve_small<256, true>(s_subh, s_krH, lane, b, k2);
        if (lane == 0) { s_thH = (int)((thH << 8) | b); s_krH = k2; }
    } else if (wid == 1) {
        unsigned b; int k2;
        resolve_small<256, false>(s_subh + 256, s_krL, lane, b, k2);
        if (lane == 0) { s_thL = (int)((thL << 8) | b); s_krL = k2; }
    }
    __syncthreads();

    // ===== sublevel 2: bits 12..5 (256 bins) ===================================
    {
        const unsigned pH = (unsigned)s_thH;   // 19-bit prefix
        const unsigned pL = (unsigned)s_thL;
        s_subh[tid] = 0;
        s_subh[tid + 256] = 0;
        __syncthreads();
        for (int t = tid; t < cntH; t += THREADS) {
            unsigned key = f2key(s_val[t]);
            if ((key >> 13) == pH) atomicAdd(&s_subh[(key >> 5) & 0xFFu], 1u);
        }
        for (int t = tid; t < cntL; t += THREADS) {
            float f = sameBin ? s_val[t] : s_val[MAXN - 1 - t];
            unsigned key = f2key(f);
            if ((key >> 13) == pL) atomicAdd(&s_subh[256 + ((key >> 5) & 0xFFu)], 1u);
        }
        __syncthreads();
        if (wid == 0) {
            unsigned b; int k2;
            resolve_small<256, true>(s_subh, s_krH, lane, b, k2);
            if (lane == 0) { s_thH = (int)((pH << 8) | b); s_krH = k2; }
        } else if (wid == 1) {
            unsigned b; int k2;
            resolve_small<256, false>(s_subh + 256, s_krL, lane, b, k2);
            if (lane == 0) { s_thL = (int)((pL << 8) | b); s_krL = k2; }
        }
        __syncthreads();
    }

    // ===== sublevel 3: bits 4..0 (32 bins) =====================================
    {
        const unsigned pH = (unsigned)s_thH;   // 27-bit prefix
        const unsigned pL = (unsigned)s_thL;
        if (tid < 32) { s_subh[tid] = 0; s_subh[tid + 256] = 0; }
        __syncthreads();
        for (int t = tid; t < cntH; t += THREADS) {
            unsigned key = f2key(s_val[t]);
            if ((key >> 5) == pH) atomicAdd(&s_subh[key & 0x1Fu], 1u);
        }
        for (int t = tid; t < cntL; t += THREADS) {
            float f = sameBin ? s_val[t] : s_val[MAXN - 1 - t];
            unsigned key = f2key(f);
            if ((key >> 5) == pL) atomicAdd(&s_subh[256 + (key & 0x1Fu)], 1u);
        }
        __syncthreads();
        if (wid == 0) {
            unsigned b; int k2;
            resolve_small<32, true>(s_subh, s_krH, lane, b, k2);
            if (lane == 0) { s_thH = (int)((pH << 5) | b); s_krH = k2; }
        } else if (wid == 1) {
            unsigned b; int k2;
            resolve_small<32, false>(s_subh + 256, s_krL, lane, b, k2);
            if (lane == 0) { s_thL = (int)((pL << 5) | b); s_krL = k2; }
        }
        __syncthreads();
    }

    const unsigned keyH = (unsigned)s_thH;   // full 32-bit key of kth largest
    const unsigned keyL = (unsigned)s_thL;   // full 32-bit key of kth smallest

    // ===== final sweep over candidates (strictly above / below) ===============
    for (int t = tid; t < cntH; t += THREADS) {
        float f = s_val[t];
        if (f2key(f) > keyH) sumT += f;
    }
    for (int t = tid; t < cntL; t += THREADS) {
        float f = sameBin ? s_val[t] : s_val[MAXN - 1 - t];
        if (f2key(f) < keyL) sumB += f;
    }

    #pragma unroll
    for (int o = 16; o > 0; o >>= 1) {
        sumT += __shfl_xor_sync(0xFFFFFFFFu, sumT, o);
        sumB += __shfl_xor_sync(0xFFFFFFFFu, sumB, o);
    }
    if (lane == 0) { s_redf[0][wid] = sumT; s_redf[1][wid] = sumB; }
    __syncthreads();

    if (tid == 0) {
        float st = 0.0f, sb = 0.0f;
        #pragma unroll
        for (int w = 0; w < THREADS / 32; ++w) { st += s_redf[0][w]; sb += s_redf[1][w]; }
        st += (float)s_krH * key2f(keyH);   // exact tie handling
        sb += (float)s_krL * key2f(keyL);
        out[row] = st / (float)kmax + (alpha / (float)kmin) * sb;
    }
}

extern "C" void kernel_launch(void* const* d_in, const int* in_sizes, int n_in,
                              void* d_out, int out_size)
{
    const float* x = (const float*)d_in[0];
    float* out = (float*)d_out;

    const int rows = out_size;                 // 32*512 = 16384
    const int n = in_sizes[0] / rows;          // 4096
    int kmax = (int)lrintf(0.2f * (float)n);   // int(round(0.2*n)) = 819
    int kmin = (int)lrintf(0.2f * (float)n);
    if (kmax < 1) kmax = 1;
    if (kmin < 1) kmin = 1;

    wildcat_kernel<<<rows, THREADS>>>(x, out, n, kmax, kmin, 0.7f);
}

// round 11
// speedup vs baseline: 1.2742x; 1.2742x over previous
#include <cuda_runtime.h>
#include <math.h>

#define THREADS 256
#define ELEMS   16
#define NFAST   (THREADS * ELEMS)   // 4096
#define CAP     2048                // per-side candidate cap

// Order-preserving float->uint key: monotonic increasing with float value.
__device__ __forceinline__ unsigned f2key(float v) {
    unsigned u = __float_as_uint(v);
    return u ^ (unsigned)(((int)u >> 31) | 0x80000000u);
}
__device__ __forceinline__ float key2f(unsigned key) {
    unsigned u = (key & 0x80000000u) ? (key ^ 0x80000000u) : ~key;
    return __uint_as_float(u);
}

// Warp-collective small resolve: bin containing krem-th element
// (DESC = counted from top bin downward). Returns bin + residual rank.
template<int NB, bool DESC>
__device__ __forceinline__ void resolve_small(const unsigned* __restrict__ hist, int krem,
                                              int lane, unsigned &bin, int &krem_out)
{
    constexpr int BPL = NB / 32;
    unsigned s = 0;
    #pragma unroll
    for (int j = 0; j < BPL; j++) {
        int b = DESC ? (NB - 1 - (lane * BPL + j)) : (lane * BPL + j);
        s += hist[b];
    }
    unsigned p = s;
    #pragma unroll
    for (int o = 1; o < 32; o <<= 1) {
        unsigned t = __shfl_up_sync(0xFFFFFFFFu, p, o);
        if (lane >= o) p += t;
    }
    unsigned excl = p - s;
    bool cross = (excl < (unsigned)krem) && (p >= (unsigned)krem);
    unsigned m = __ballot_sync(0xFFFFFFFFu, cross);
    int src = __ffs(m) - 1;
    unsigned bsel = 0; int k2 = 0;
    if (cross) {
        unsigned cum = excl;
        #pragma unroll
        for (int j = 0; j < BPL; j++) {
            int b = DESC ? (NB - 1 - (lane * BPL + j)) : (lane * BPL + j);
            unsigned c = hist[b];
            if (cum + c >= (unsigned)krem) { bsel = (unsigned)b; k2 = krem - (int)cum; break; }
            cum += c;
        }
    }
    bin = __shfl_sync(0xFFFFFFFFu, bsel, src);
    krem_out = __shfl_sync(0xFFFFFFFFu, k2, src);
}

// ========================= FAST kernel (n == 4096) ==========================
__global__ void __launch_bounds__(THREADS, 5)
wildcat_fast(const float* __restrict__ x, float* __restrict__ out,
             int kmax, int kmin, float alpha)
{
    __shared__ float     s_val[2 * CAP];     // top from 0, bottom from end
    __shared__ unsigned  s_subh[512];
    __shared__ unsigned  s_c[8];
    __shared__ unsigned  s_c2[2];
    __shared__ long long s_loT, s_hiT, s_loB, s_hiB;
    __shared__ int       s_cAloT, s_cAhiT, s_cBloB, s_cBhiB;
    __shared__ int       s_refine, s_cntH, s_cntL, s_krH, s_krL;
    __shared__ unsigned  s_selH, s_selL;
    __shared__ float     s_redf[2][THREADS / 32];

    const int tid  = threadIdx.x;
    const int lane = tid & 31;
    const int wid  = tid >> 5;
    const float* __restrict__ xr = x + (long long)blockIdx.x * NFAST;

    // ---- load 16 elements into registers (the only full-row memory pass) ----
    float v[ELEMS];
    {
        const float4* __restrict__ xr4 = (const float4*)xr;
        #pragma unroll
        for (int k = 0; k < 4; k++) {
            float4 t = xr4[tid + k * THREADS];
            v[4 * k + 0] = t.x; v[4 * k + 1] = t.y;
            v[4 * k + 2] = t.z; v[4 * k + 3] = t.w;
        }
    }
    if (tid < 8) s_c[tid] = 0;
    if (tid == 0) { s_cntH = 0; s_cntL = 0; }
    __syncthreads();

    // ---- sweep A: register-resident probe counts (pure ALU, no L1) ----
    unsigned a0=0,a1=0,a2=0,a3=0,c0=0,c1=0,c2=0,c3=0;
    #pragma unroll
    for (int j = 0; j < ELEMS; j++) {
        float f = v[j];
        a0 += f >  0.72f; a1 += f >  0.80f; a2 += f >  0.88f; a3 += f >  0.96f;
        c0 += f < -0.96f; c1 += f < -0.88f; c2 += f < -0.80f; c3 += f < -0.72f;
    }
    a0 = __reduce_add_sync(0xFFFFFFFFu, a0);
    a1 = __reduce_add_sync(0xFFFFFFFFu, a1);
    a2 = __reduce_add_sync(0xFFFFFFFFu, a2);
    a3 = __reduce_add_sync(0xFFFFFFFFu, a3);
    c0 = __reduce_add_sync(0xFFFFFFFFu, c0);
    c1 = __reduce_add_sync(0xFFFFFFFFu, c1);
    c2 = __reduce_add_sync(0xFFFFFFFFu, c2);
    c3 = __reduce_add_sync(0xFFFFFFFFu, c3);
    if (lane == 0) {
        atomicAdd(&s_c[0], a0); atomicAdd(&s_c[1], a1);
        atomicAdd(&s_c[2], a2); atomicAdd(&s_c[3], a3);
        atomicAdd(&s_c[4], c0); atomicAdd(&s_c[5], c1);
        atomicAdd(&s_c[6], c2); atomicAdd(&s_c[7], c3);
    }
    __syncthreads();

    // ---- bracket selection from probe counts ----
    if (tid == 0) {
        const float pT[4] = {0.72f, 0.80f, 0.88f, 0.96f};
        const float pB[4] = {-0.96f, -0.88f, -0.80f, -0.72f};
        unsigned km = (unsigned)kmax, kn = (unsigned)kmin;
        long long lo, hi; int cAlo, cAhi;
        if (s_c[0] < km)       { lo = -1;                      hi = (long long)f2key(pT[0]); cAlo = NFAST;       cAhi = (int)s_c[0]; }
        else if (s_c[3] >= km) { lo = (long long)f2key(pT[3]); hi = 0xFFFFFFFFLL;            cAlo = (int)s_c[3]; cAhi = 0; }
        else {
            int j = (s_c[2] >= km) ? 2 : (s_c[1] >= km) ? 1 : 0;
            lo = (long long)f2key(pT[j]); hi = (long long)f2key(pT[j + 1]);
            cAlo = (int)s_c[j]; cAhi = (int)s_c[j + 1];
        }
        s_loT = lo; s_hiT = hi; s_cAloT = cAlo; s_cAhiT = cAhi;

        long long lob, hib; int cBlo, cBhi;
        if (s_c[7] < kn)       { lob = (long long)f2key(pB[3]); hib = 0x100000000LL;           cBlo = (int)s_c[7]; cBhi = NFAST; }
        else if (s_c[4] >= kn) { lob = 0;                       hib = (long long)f2key(pB[0]); cBlo = 0;           cBhi = (int)s_c[4]; }
        else {
            int j = (s_c[5] >= kn) ? 0 : (s_c[6] >= kn) ? 1 : 2;
            lob = (long long)f2key(pB[j]); hib = (long long)f2key(pB[j + 1]);
            cBlo = (int)s_c[4 + j]; cBhi = (int)s_c[4 + j + 1];
        }
        s_loB = lob; s_hiB = hib; s_cBloB = cBlo; s_cBhiB = cBhi;

        bool needT = (cAlo - cAhi > CAP) && (hi - lo > 1);
        bool needB = (cBhi - cBlo > CAP) && (hib - lob > 1);
        s_refine = (needT || needB) ? 1 : 0;
    }
    __syncthreads();

    // ---- exact binary-search refinement (rare; key-space, register counts) --
    while (true) {
        if (!s_refine) break;
        if (tid < 2) s_c2[tid] = 0;
        const long long midT = (s_loT + s_hiT) >> 1;
        const long long midB = (s_loB + s_hiB) >> 1;
        __syncthreads();
        unsigned ct = 0, cb = 0;
        #pragma unroll
        for (int j = 0; j < ELEMS; j++) {
            long long k = (long long)f2key(v[j]);
            ct += (k > midT);
            cb += (k < midB);
        }
        ct = __reduce_add_sync(0xFFFFFFFFu, ct);
        cb = __reduce_add_sync(0xFFFFFFFFu, cb);
        if (lane == 0) { atomicAdd(&s_c2[0], ct); atomicAdd(&s_c2[1], cb); }
        __syncthreads();
        if (tid == 0) {
            bool needT = (s_cAloT - s_cAhiT > CAP) && (s_hiT - s_loT > 1);
            if (needT) {
                int c = (int)s_c2[0];
                if (c >= kmax) { s_loT = midT; s_cAloT = c; }
                else           { s_hiT = midT; s_cAhiT = c; }
            }
            bool needB = (s_cBhiB - s_cBloB > CAP) && (s_hiB - s_loB > 1);
            if (needB) {
                int c = (int)s_c2[1];
                if (c >= kmin) { s_hiB = midB; s_cBhiB = c; }
                else           { s_loB = midB; s_cBloB = c; }
            }
            needT = (s_cAloT - s_cAhiT > CAP) && (s_hiT - s_loT > 1);
            needB = (s_cBhiB - s_cBloB > CAP) && (s_hiB - s_loB > 1);
            s_refine = (needT || needB) ? 1 : 0;
        }
        __syncthreads();
    }

    const long long loT = s_loT, hiT = s_hiT, loB = s_loB, hiB = s_hiB;
    const bool skipT = (hiT - loT) == 1;    // all candidates share one key
    const bool skipB = (hiB - loB) == 1;

    // ---- sweep B: strict-side sums + candidate compaction (registers) -------
    float sumT = 0.0f, sumB = 0.0f;
    #pragma unroll
    for (int j = 0; j < ELEMS; j++) {
        float f = v[j];
        long long k = (long long)f2key(f);
        if (k > hiT) sumT += f;
        else if (!skipT && k > loT) { int p = atomicAdd(&s_cntH, 1); s_val[p] = f; }
        if (k < loB) sumB += f;
        else if (!skipB && k < hiB) { int p = atomicAdd(&s_cntL, 1); s_val[2 * CAP - 1 - p] = f; }
    }
    if (tid == 0) { s_selH = 0; s_selL = 0; s_krH = kmax - s_cAhiT; s_krL = kmin - s_cBloB; }
    __syncthreads();

    const int cntH = s_cntH, cntL = s_cntL;

    // ---- exact 4-level radix select over tiny candidate lists ---------------
    if (!skipT || !skipB) {
        // level 0 (bits 31..24)
        s_subh[tid] = 0; s_subh[tid + 256] = 0;
        __syncthreads();
        if (!skipT) for (int t = tid; t < cntH; t += THREADS)
            atomicAdd(&s_subh[f2key(s_val[t]) >> 24], 1u);
        if (!skipB) for (int t = tid; t < cntL; t += THREADS)
            atomicAdd(&s_subh[256 + (f2key(s_val[2 * CAP - 1 - t]) >> 24)], 1u);
        __syncthreads();
        if (wid == 0 && !skipT) {
            unsigned b; int k2;
            resolve_small<256, true>(s_subh, s_krH, lane, b, k2);
            if (lane == 0) { s_selH = b; s_krH = k2; }
        } else if (wid == 1 && !skipB) {
            unsigned b; int k2;
            resolve_small<256, false>(s_subh + 256, s_krL, lane, b, k2);
            if (lane == 0) { s_selL = b; s_krL = k2; }
        }
        __syncthreads();
        // levels 1..3
        #pragma unroll 1
        for (int l = 1; l < 4; l++) {
            const int fsh = 32 - 8 * l;
            const int dsh = 24 - 8 * l;
            const unsigned pH = s_selH, pL = s_selL;
            s_subh[tid] = 0; s_subh[tid + 256] = 0;
            __syncthreads();
            if (!skipT) for (int t = tid; t < cntH; t += THREADS) {
                unsigned key = f2key(s_val[t]);
                if ((key >> fsh) == pH) atomicAdd(&s_subh[(key >> dsh) & 0xFFu], 1u);
            }
            if (!skipB) for (int t = tid; t < cntL; t += THREADS) {
                unsigned key = f2key(s_val[2 * CAP - 1 - t]);
                if ((key >> fsh) == pL) atomicAdd(&s_subh[256 + ((key >> dsh) & 0xFFu)], 1u);
            }
            __syncthreads();
            if (wid == 0 && !skipT) {
                unsigned b; int k2;
                resolve_small<256, true>(s_subh, s_krH, lane, b, k2);
                if (lane == 0) { s_selH = (pH << 8) | b; s_krH = k2; }
            } else if (wid == 1 && !skipB) {
                unsigned b; int k2;
                resolve_small<256, false>(s_subh + 256, s_krL, lane, b, k2);
                if (lane == 0) { s_selL = (pL << 8) | b; s_krL = k2; }
            }
            __syncthreads();
        }
    }

    const unsigned keyH = skipT ? (unsigned)hiT : s_selH;
    const unsigned keyL = skipB ? (unsigned)loB : s_selL;

    // ---- final tiny sweep over candidates (strictly above / below) ----------
    for (int t = tid; t < cntH; t += THREADS) {
        float f = s_val[t];
        if (f2key(f) > keyH) sumT += f;
    }
    for (int t = tid; t < cntL; t += THREADS) {
        float f = s_val[2 * CAP - 1 - t];
        if (f2key(f) < keyL) sumB += f;
    }
    #pragma unroll
    for (int o = 16; o > 0; o >>= 1) {
        sumT += __shfl_xor_sync(0xFFFFFFFFu, sumT, o);
        sumB += __shfl_xor_sync(0xFFFFFFFFu, sumB, o);
    }
    if (lane == 0) { s_redf[0][wid] = sumT; s_redf[1][wid] = sumB; }
    __syncthreads();

    if (tid == 0) {
        float st = 0.0f, sb = 0.0f;
        #pragma unroll
        for (int w = 0; w < THREADS / 32; ++w) { st += s_redf[0][w]; sb += s_redf[1][w]; }
        st += (float)s_krH * key2f(keyH);    // exact tie handling
        sb += (float)s_krL * key2f(keyL);
        out[blockIdx.x] = st / (float)kmax + (alpha / (float)kmin) * sb;
    }
}

// ================= GENERIC fallback (any n) — proven R8 path ================
template<bool DESC>
__device__ __forceinline__ void resolve_big(const unsigned* __restrict__ hist, int krem,
                                            int lane, unsigned &bin, int &krem_out)
{
    const uint4* h4 = (const uint4*)hist;
    unsigned s = 0;
    #pragma unroll
    for (int j = 0; j < 32; j++) {
        uint4 c = h4[lane * 32 + j];
        s += c.x + c.y + c.z + c.w;
    }
    unsigned p = s;
    if (DESC) {
        #pragma unroll
        for (int o = 1; o < 32; o <<= 1) {
            unsigned t = __shfl_down_sync(0xFFFFFFFFu, p, o);
            if (lane + o < 32) p += t;
        }
    } else {
        #pragma unroll
        for (int o = 1; o < 32; o <<= 1) {
            unsigned t = __shfl_up_sync(0xFFFFFFFFu, p, o);
            if (lane >= o) p += t;
        }
    }
    unsigned excl = p - s;
    bool cross = (excl < (unsigned)krem) && (p >= (unsigned)krem);
    unsigned m = __ballot_sync(0xFFFFFFFFu, cross);
    int src = __ffs(m) - 1;
    unsigned bsel = 0; int k2 = 0;
    if (cross) {
        unsigned cum = excl;
        if (DESC) {
            for (int b = lane * 128 + 127; b >= lane * 128; --b) {
                unsigned c = hist[b];
                if (cum + c >= (unsigned)krem) { bsel = (unsigned)b; k2 = krem - (int)cum; break; }
                cum += c;
            }
        } else {
            for (int b = lane * 128; b < lane * 128 + 128; ++b) {
                unsigned c = hist[b];
                if (cum + c >= (unsigned)krem) { bsel = (unsigned)b; k2 = krem - (int)cum; break; }
                cum += c;
            }
        }
    }
    bin = __shfl_sync(0xFFFFFFFFu, bsel, src);
    krem_out = __shfl_sync(0xFFFFFFFFu, k2, src);
}

__global__ void __launch_bounds__(THREADS, 8)
wildcat_generic(const float* __restrict__ x, float* __restrict__ out,
                int n, int kmax, int kmin, float alpha)
{
    __shared__ unsigned s_mem[4096];
    __shared__ unsigned s_subh[512];
    __shared__ unsigned s_selH, s_selL;
    __shared__ int      s_kremH, s_kremL, s_cntH, s_cntL;
    __shared__ float    s_red[2][THREADS / 32];
    float* s_val = (float*)s_mem;

    const int tid  = threadIdx.x;
    const int lane = tid & 31;
    const int wid  = tid >> 5;
    const float* __restrict__ xr = x + (long long)blockIdx.x * n;

    for (int b = tid; b < 4096; b += THREADS) s_mem[b] = 0;
    if (tid == 0) { s_cntH = 0; s_cntL = 0; }
    __syncthreads();

    for (int i = tid; i < n; i += THREADS)
        atomicAdd(&s_mem[f2key(xr[i]) >> 20], 1u);
    __syncthreads();

    if (wid == 0) {
        unsigned b; int k2;
        resolve_big<true>(s_mem, kmax, lane, b, k2);
        if (lane == 0) { s_selH = b; s_kremH = k2; }
    } else if (wid == 1) {
        unsigned b; int k2;
        resolve_big<false>(s_mem, kmin, lane, b, k2);
        if (lane == 0) { s_selL = b; s_kremL = k2; }
    }
    __syncthreads();
    const unsigned binH = s_selH, binL = s_selL;
    const bool sameBin = (binH == binL);
    __syncthreads();

    float sumT = 0.0f, sumB = 0.0f;
    for (int i = tid; i < n; i += THREADS) {
        float f = xr[i];
        unsigned b = f2key(f) >> 20;
        if (b > binH) sumT += f;
        if (b < binL) sumB += f;
        if (b == binH) { int p = atomicAdd(&s_cntH, 1); s_val[p] = f; }
        else if (b == binL) { int p = atomicAdd(&s_cntL, 1); s_val[4095 - p] = f; }
    }
    __syncthreads();
    const int cntH = min(s_cntH, 4096);
    const int cntL = sameBin ? cntH : min(s_cntL, 4096);

    #pragma unroll 1
    for (int l = 0; l < 3; l++) {
        const int fsh = 20 - 8 * l + 8;       // 28,20,12 -> use (key>>(20-8l+?)) pattern below
        (void)fsh;
        const int fs = (l == 0) ? 20 : (l == 1) ? 12 : 6;
        const int sh = (l == 0) ? 12 : (l == 1) ? 6 : 0;
        const unsigned mk = (l == 0) ? 0xFFu : 0x3Fu;
        const int nb = (l == 0) ? 256 : 64;
        const unsigned pH = s_selH, pL = s_selL;
        if (tid < nb) { s_subh[tid] = 0; s_subh[tid + 256] = 0; }
        __syncthreads();
        for (int t = tid; t < cntH; t += THREADS) {
            unsigned key = f2key(s_val[t]);
            if ((key >> fs) == pH) atomicAdd(&s_subh[(key >> sh) & mk], 1u);
        }
        for (int t = tid; t < cntL; t += THREADS) {
            float f = sameBin ? s_val[t] : s_val[4095 - t];
            unsigned key = f2key(f);
            if ((key >> fs) == pL) atomicAdd(&s_subh[256 + ((key >> sh) & mk)], 1u);
        }
        __syncthreads();
        if (wid == 0) {
            unsigned b; int k2;
            if (nb == 256) resolve_small<256, true>(s_subh, s_kremH, lane, b, k2);
            else           resolve_small<64,  true>(s_subh, s_kremH, lane, b, k2);
            if (lane == 0) { s_selH = (pH << ((l == 0) ? 8 : 6)) | b; s_kremH = k2; }
        } else if (wid == 1) {
            unsigned b; int k2;
            if (nb == 256) resolve_small<256, false>(s_subh + 256, s_kremL, lane, b, k2);
            else           resolve_small<64,  false>(s_subh + 256, s_kremL, lane, b, k2);
            if (lane == 0) { s_selL = (pL << ((l == 0) ? 8 : 6)) | b; s_kremL = k2; }
        }
        __syncthreads();
    }

    const unsigned keyH = s_selH, keyL = s_selL;
    for (int t = tid; t < cntH; t += THREADS) {
        float f = s_val[t];
        if (f2key(f) > keyH) sumT += f;
    }
    for (int t = tid; t < cntL; t += THREADS) {
        float f = sameBin ? s_val[t] : s_val[4095 - t];
        if (f2key(f) < keyL) sumB += f;
    }
    #pragma unroll
    for (int o = 16; o > 0; o >>= 1) {
        sumT += __shfl_xor_sync(0xFFFFFFFFu, sumT, o);
        sumB += __shfl_xor_sync(0xFFFFFFFFu, sumB, o);
    }
    if (lane == 0) { s_red[0][wid] = sumT; s_red[1][wid] = sumB; }
    __syncthreads();
    if (tid == 0) {
        float st = 0.0f, sb = 0.0f;
        #pragma unroll
        for (int w = 0; w < THREADS / 32; ++w) { st += s_red[0][w]; sb += s_red[1][w]; }
        st += (float)s_kremH * key2f(keyH);
        sb += (float)s_kremL * key2f(keyL);
        out[blockIdx.x] = st / (float)kmax + (alpha / (float)kmin) * sb;
    }
}

extern "C" void kernel_launch(void* const* d_in, const int* in_sizes, int n_in,
                              void* d_out, int out_size)
{
    const float* x = (const float*)d_in[0];
    float* out = (float*)d_out;

    const int rows = out_size;                 // 32*512 = 16384
    const int n = in_sizes[0] / rows;          // 4096
    int kmax = (int)lrintf(0.2f * (float)n);   // int(round(0.2*n)) = 819
    int kmin = (int)lrintf(0.2f * (float)n);
    if (kmax < 1) kmax = 1;
    if (kmin < 1) kmin = 1;

    if (n == NFAST)
        wildcat_fast<<<rows, THREADS>>>(x, out, kmax, kmin, 0.7f);
    else
        wildcat_generic<<<rows, THREADS>>>(x, out, n, kmax, kmin, 0.7f);
}